// round 9
// baseline (speedup 1.0000x reference)
#include <cuda_runtime.h>
#include <stdint.h>
#include <math.h>

#define SEQN 320
#define HN   400
#define GN   1600
#define NP1  321
#define CLU  16          // CTAs per direction (cluster size, non-portable)
#define DPC  25          // h-dims per CTA
#define TPB  416         // 13 warps; 26 groups of 16 lanes (group 25 is dummy)
#define HPAD 448         // padded h buffer: 16 chunks * 28 floats

// ---------------- scratch (static device globals; no allocation) ----------------
__device__ float g_x[SEQN * HN];            // [320][400] embeddings
__device__ float g_G0[2][SEQN * GN];        // layer0 input projections (fwd, bwd)
__device__ float g_G1[2][SEQN * GN];        // layer1 input projections
__device__ float g_y0[SEQN * 800];          // layer0 bilstm output
__device__ float g_hv[SEQN * 800];          // layer1 bilstm output
__device__ float g_A[SEQN * GN];            // hv @ w1a.T
__device__ float g_B[SEQN * GN];            // hv @ w1b.T

// ---------------- embedding gather ----------------
__global__ void k_embed(const int* __restrict__ words, const int* __restrict__ tags,
                        const float* __restrict__ wemb, const float* __restrict__ temb) {
    int idx = blockIdx.x * blockDim.x + threadIdx.x;
    if (idx >= SEQN * HN) return;
    int t = idx / HN, j = idx % HN;
    g_x[idx] = (j < 300) ? wemb[(size_t)words[t] * 300 + j]
                         : temb[(size_t)tags[t] * 100 + (j - 300)];
}

// ---------------- fused dual NT GEMM, 32x64 tiles for occupancy -------------
// C[320][1600] = X[320][K] * W[:, wofs:wofs+K].T + b1 + b2   (two problems via z)
__global__ void __launch_bounds__(256)
k_gemm2(const float* __restrict__ X, int ldx,
        const float* __restrict__ W0, const float* __restrict__ W1, int ldw,
        int wofs0, int wofs1,
        const float* __restrict__ b1a, const float* __restrict__ b1b,
        const float* __restrict__ b2a, const float* __restrict__ b2b,
        float* __restrict__ C0, float* __restrict__ C1, int K) {
    const float* W   = blockIdx.z ? W1 : W0;
    const int   wofs = blockIdx.z ? wofs1 : wofs0;
    const float* b1  = blockIdx.z ? b1b : b1a;
    const float* b2  = blockIdx.z ? b2b : b2a;
    float*       C   = blockIdx.z ? C1 : C0;

    __shared__ __align__(16) float Xs[16][32];
    __shared__ __align__(16) float Ws[16][64];
    int tid = threadIdx.x;
    int tx = tid & 15, ty = tid >> 4;      // tx: 4-col group, ty: 2-row group
    int row0 = blockIdx.x * 32, col0 = blockIdx.y * 64;
    int lk = tid & 15, lm = tid >> 4;

    float acc[2][4] = {};

    for (int k0 = 0; k0 < K; k0 += 16) {
        // Xs: 16k x 32m (2 per thread), Ws: 16k x 64m (4 per thread)
#pragma unroll
        for (int p = 0; p < 2; p++)
            Xs[lk][lm + p * 16] = X[(size_t)(row0 + lm + p * 16) * ldx + k0 + lk];
#pragma unroll
        for (int p = 0; p < 4; p++)
            Ws[lk][lm + p * 16] = W[(size_t)(col0 + lm + p * 16) * ldw + wofs + k0 + lk];
        __syncthreads();
#pragma unroll
        for (int kk = 0; kk < 16; kk++) {
            float a0 = Xs[kk][2 * ty];
            float a1 = Xs[kk][2 * ty + 1];
            float4 b = *reinterpret_cast<const float4*>(&Ws[kk][tx * 4]);
            float bv[4] = {b.x, b.y, b.z, b.w};
#pragma unroll
            for (int j = 0; j < 4; j++) {
                acc[0][j] = fmaf(a0, bv[j], acc[0][j]);
                acc[1][j] = fmaf(a1, bv[j], acc[1][j]);
            }
        }
        __syncthreads();
    }
#pragma unroll
    for (int i = 0; i < 2; i++) {
#pragma unroll
        for (int j = 0; j < 4; j++) {
            int n = col0 + tx * 4 + j;
            float bias = 0.f;
            if (b1) bias += b1[n];
            if (b2) bias += b2[n];
            C[(size_t)(row0 + 2 * ty + i) * GN + n] = acc[i][j] + bias;
        }
    }
}

// ---------------- cluster BiLSTM ----------------
__device__ __forceinline__ float sig_fast(float x) {
    return __fdividef(1.f, 1.f + __expf(-x));
}
__device__ __forceinline__ float tanh_fast(float x) {
    return fmaf(2.f, __fdividef(1.f, 1.f + __expf(-2.f * x)), -1.f);
}
__device__ __forceinline__ uint32_t s2u(const void* p) {
    uint32_t a;
    asm("{ .reg .u64 t; cvta.to.shared.u64 t, %1; cvt.u32.u64 %0, t; }" : "=r"(a) : "l"(p));
    return a;
}

// grid (32), cluster (16): blocks 0-15 = forward, 16-31 = backward.
// CTA owns 25 h-dims; thread t: grp = t>>4 (dim), lc = t&15 (25-elem chunk of h).
// h double-buffered in padded SMEM (28-float chunk stride -> float4 reads).
// After the 16-lane reduction every lane has all 4 gate sums; each lane
// redundantly computes c/h and stores hN to cluster rank lc (one warp-wide
// st.shared::cluster replaces the old leader 16-store loop).
__global__ void __launch_bounds__(TPB, 1)
k_lstm(const float* __restrict__ whh_f, const float* __restrict__ whh_b,
       const float* __restrict__ h0, const float* __restrict__ c0, int layer) {
    const int dir = blockIdx.x >> 4;
    const int cta = blockIdx.x & 15;
    const float* G   = (layer == 0) ? g_G0[dir] : g_G1[dir];
    float*       Y   = (layer == 0) ? g_y0 : g_hv;
    const float* whh = dir ? whh_b : whh_f;
    const float* h0row = h0 + (size_t)(2 * layer + dir) * HN;
    const float* c0row = c0 + (size_t)(2 * layer + dir) * HN;

    const int tid = threadIdx.x;
    const int grp = tid >> 4;        // 0..25 (25 = dummy)
    const int lc  = tid & 15;        // h-chunk id
    const bool active = grp < DPC;
    const int dim = cta * DPC + grp;

    __shared__ __align__(16) float sh_h[2][HPAD];

    // register-resident recurrent weights (lane lc covers h dims [lc*25, lc*25+25))
    float wI[25], wF[25], wGc[25], wO[25];
    if (active) {
        const float* pI = whh + (size_t)(dim)        * HN + lc * 25;
        const float* pF = whh + (size_t)(400 + dim)  * HN + lc * 25;
        const float* pG = whh + (size_t)(800 + dim)  * HN + lc * 25;
        const float* pO = whh + (size_t)(1200 + dim) * HN + lc * 25;
#pragma unroll
        for (int d = 0; d < 25; d++) {
            wI[d] = __ldg(pI + d); wF[d] = __ldg(pF + d);
            wGc[d] = __ldg(pG + d); wO[d] = __ldg(pO + d);
        }
    } else {
#pragma unroll
        for (int d = 0; d < 25; d++) { wI[d] = 0.f; wF[d] = 0.f; wGc[d] = 0.f; wO[d] = 0.f; }
    }

    float cst = active ? __ldg(c0row + dim) : 0.f;   // all lanes (redundant, identical)

    // init buffer 0 with h0 in padded layout
    for (int i = tid; i < HN; i += TPB)
        sh_h[0][(i / 25) * 28 + (i % 25)] = h0row[i];
    __syncthreads();

    // precompute this lane's remote store addresses (rank = lc), both buffers
    const uint32_t lbase = s2u(&sh_h[0][0]);
    uint32_t raddr0;
    {
        uint32_t la = lbase + (uint32_t)((cta * 28 + grp) * 4);
        asm("mapa.shared::cluster.u32 %0, %1, %2;" : "=r"(raddr0) : "r"(la), "r"(lc));
    }
    const uint32_t raddr1 = raddr0 + HPAD * 4;

    // prefetch G gates for step 0 (uniform across the 16 lanes of a group)
    float gi = 0.f, gf = 0.f, gg = 0.f, go = 0.f;
    if (active) {
        const float* gr = G + (size_t)(dir ? SEQN - 1 : 0) * GN + dim;
        gi = __ldg(gr); gf = __ldg(gr + 400); gg = __ldg(gr + 800); go = __ldg(gr + 1200);
    }

    for (int s = 0; s < SEQN; ++s) {
        const int buf = s & 1;
        const int t = dir ? (SEQN - 1 - s) : s;

        // dot over this lane's 25-elem chunk: 6 x float4 + 1 scalar
        float ai = 0.f, af = 0.f, ag = 0.f, ao = 0.f;
        const float4* hv4 = reinterpret_cast<const float4*>(&sh_h[buf][lc * 28]);
#pragma unroll
        for (int j = 0; j < 6; j++) {
            float4 v = hv4[j];
            ai = fmaf(wI[4*j],   v.x, ai); af = fmaf(wF[4*j],   v.x, af);
            ag = fmaf(wGc[4*j],  v.x, ag); ao = fmaf(wO[4*j],   v.x, ao);
            ai = fmaf(wI[4*j+1], v.y, ai); af = fmaf(wF[4*j+1], v.y, af);
            ag = fmaf(wGc[4*j+1],v.y, ag); ao = fmaf(wO[4*j+1], v.y, ao);
            ai = fmaf(wI[4*j+2], v.z, ai); af = fmaf(wF[4*j+2], v.z, af);
            ag = fmaf(wGc[4*j+2],v.z, ag); ao = fmaf(wO[4*j+2], v.z, ao);
            ai = fmaf(wI[4*j+3], v.w, ai); af = fmaf(wF[4*j+3], v.w, af);
            ag = fmaf(wGc[4*j+3],v.w, ag); ao = fmaf(wO[4*j+3], v.w, ao);
        }
        {
            float v = sh_h[buf][lc * 28 + 24];
            ai = fmaf(wI[24], v, ai); af = fmaf(wF[24], v, af);
            ag = fmaf(wGc[24], v, ag); ao = fmaf(wO[24], v, ao);
        }
        // reduce across 16 lanes of the group (xor <= 8 stays within group)
#pragma unroll
        for (int m = 8; m >= 1; m >>= 1) {
            ai += __shfl_xor_sync(0xffffffffu, ai, m);
            af += __shfl_xor_sync(0xffffffffu, af, m);
            ag += __shfl_xor_sync(0xffffffffu, ag, m);
            ao += __shfl_xor_sync(0xffffffffu, ao, m);
        }

        if (active) {
            // all 16 lanes compute identical results
            float I  = sig_fast(gi + ai);
            float F  = sig_fast(gf + af);
            float O  = sig_fast(go + ao);
            float Gv = tanh_fast(gg + ag);
            cst = fmaf(F, cst, I * Gv);
            float hN = O * tanh_fast(cst);
            if (lc == 0) Y[(size_t)t * 800 + dir * HN + dim] = hN;
            // lane lc stores hN into rank lc's next buffer (one warp-wide store)
            uint32_t ra = buf ? raddr0 : raddr1;
            asm volatile("st.shared::cluster.f32 [%0], %1;" :: "r"(ra), "f"(hN) : "memory");
        }

        // prefetch next step's G gates (independent of h)
        if (active && s + 1 < SEQN) {
            const int tn = dir ? (SEQN - 2 - s) : (s + 1);
            const float* gr = G + (size_t)tn * GN + dim;
            gi = __ldg(gr); gf = __ldg(gr + 400); gg = __ldg(gr + 800); go = __ldg(gr + 1200);
        }

        // cluster barrier: release DSMEM stores / acquire before next reads
        asm volatile("barrier.cluster.arrive.aligned;" ::: "memory");
        asm volatile("barrier.cluster.wait.aligned;" ::: "memory");
    }
}

// ---------------- output border (row 0 / col 0, corner) ----------------
__global__ void k_border(float* __restrict__ out) {
    int i = threadIdx.x;
    if (i < NP1) {
        out[i] = (i == 0) ? 1.f : 0.f;
        if (i > 0) out[(size_t)i * NP1] = 0.f;
    }
}

// ---------------- pairwise scorer ----------------
__global__ void __launch_bounds__(256)
k_scores(const float* __restrict__ b1v, const float* __restrict__ w2,
         const float* __restrict__ b2, float* __restrict__ out) {
    __shared__ float As[32][65];
    __shared__ float Bs[32][65];
    __shared__ float w2s[64];
    int tid = threadIdx.x;
    int tx = tid & 15, ty = tid >> 4;
    int i0 = blockIdx.y * 32, j0 = blockIdx.x * 32;

    float acc[2][2] = {};

    for (int k0 = 0; k0 < GN; k0 += 64) {
        int c = tid & 63;
        int rbase = tid >> 6;
        float bb = __ldg(b1v + k0 + c);
#pragma unroll
        for (int p = 0; p < 8; p++) {
            int rr = rbase + p * 4;
            As[rr][c] = g_A[(size_t)(i0 + rr) * GN + k0 + c] + bb;
            Bs[rr][c] = g_B[(size_t)(j0 + rr) * GN + k0 + c];
        }
        if (tid < 64) w2s[tid] = w2[k0 + tid];
        __syncthreads();
#pragma unroll 8
        for (int kk = 0; kk < 64; kk++) {
            float w  = w2s[kk];
            float a0 = As[2 * ty][kk],  a1  = As[2 * ty + 1][kk];
            float b0 = Bs[2 * tx][kk],  b1_ = Bs[2 * tx + 1][kk];
            acc[0][0] = fmaf(fmaxf(a0 + b0, 0.f), w, acc[0][0]);
            acc[0][1] = fmaf(fmaxf(a0 + b1_, 0.f), w, acc[0][1]);
            acc[1][0] = fmaf(fmaxf(a1 + b0, 0.f), w, acc[1][0]);
            acc[1][1] = fmaf(fmaxf(a1 + b1_, 0.f), w, acc[1][1]);
        }
        __syncthreads();
    }
    float bb2 = __ldg(b2);
#pragma unroll
    for (int ii = 0; ii < 2; ii++)
#pragma unroll
        for (int jj = 0; jj < 2; jj++) {
            int i = i0 + 2 * ty + ii, j = j0 + 2 * tx + jj;
            float v = acc[ii][jj] + bb2;
            if (i == j) v = 0.f;
            out[(size_t)(i + 1) * NP1 + (j + 1)] = v;
        }
}

// ---------------- launch ----------------
extern "C" void kernel_launch(void* const* d_in, const int* in_sizes, int n_in,
                              void* d_out, int out_size) {
    const int*   words    = (const int*)  d_in[0];
    const int*   tags     = (const int*)  d_in[1];
    // d_in[2] = arcs (unused by reference)
    const float* wemb     = (const float*)d_in[3];
    const float* temb     = (const float*)d_in[4];
    const float* h0       = (const float*)d_in[5];
    const float* c0       = (const float*)d_in[6];
    const float* w_ih_l0  = (const float*)d_in[7];
    const float* w_hh_l0  = (const float*)d_in[8];
    const float* b_ih_l0  = (const float*)d_in[9];
    const float* b_hh_l0  = (const float*)d_in[10];
    const float* w_ih_l0r = (const float*)d_in[11];
    const float* w_hh_l0r = (const float*)d_in[12];
    const float* b_ih_l0r = (const float*)d_in[13];
    const float* b_hh_l0r = (const float*)d_in[14];
    const float* w_ih_l1  = (const float*)d_in[15];
    const float* w_hh_l1  = (const float*)d_in[16];
    const float* b_ih_l1  = (const float*)d_in[17];
    const float* b_hh_l1  = (const float*)d_in[18];
    const float* w_ih_l1r = (const float*)d_in[19];
    const float* w_hh_l1r = (const float*)d_in[20];
    const float* b_ih_l1r = (const float*)d_in[21];
    const float* b_hh_l1r = (const float*)d_in[22];
    const float* mlp_w1   = (const float*)d_in[23];
    const float* mlp_b1   = (const float*)d_in[24];
    const float* mlp_w2   = (const float*)d_in[25];
    const float* mlp_b2   = (const float*)d_in[26];
    float* out = (float*)d_out;

    float *px, *pG0, *pG1, *py0, *phv, *pA, *pB;
    cudaGetSymbolAddress((void**)&px,  g_x);
    cudaGetSymbolAddress((void**)&pG0, g_G0);
    cudaGetSymbolAddress((void**)&pG1, g_G1);
    cudaGetSymbolAddress((void**)&py0, g_y0);
    cudaGetSymbolAddress((void**)&phv, g_hv);
    cudaGetSymbolAddress((void**)&pA,  g_A);
    cudaGetSymbolAddress((void**)&pB,  g_B);
    float* pG0f = pG0;
    float* pG0b = pG0 + (size_t)SEQN * GN;
    float* pG1f = pG1;
    float* pG1b = pG1 + (size_t)SEQN * GN;

    static int attr_done = 0;
    if (!attr_done) {
        cudaFuncSetAttribute(k_lstm, cudaFuncAttributeNonPortableClusterSizeAllowed, 1);
        attr_done = 1;
    }
    cudaLaunchConfig_t cfg = {};
    cfg.gridDim  = dim3(2 * CLU, 1, 1);
    cfg.blockDim = dim3(TPB, 1, 1);
    cfg.dynamicSmemBytes = 0;
    cfg.stream = 0;
    cudaLaunchAttribute lat[1];
    lat[0].id = cudaLaunchAttributeClusterDimension;
    lat[0].val.clusterDim.x = CLU;
    lat[0].val.clusterDim.y = 1;
    lat[0].val.clusterDim.z = 1;
    cfg.attrs = lat;
    cfg.numAttrs = 1;

    dim3 gg2(10, 25, 2);   // 320/32 x 1600/64 x 2 fused problems = 500 blocks

    k_embed<<<(SEQN * HN + 255) / 256, 256>>>(words, tags, wemb, temb);

    k_gemm2<<<gg2, 256>>>(px, HN, w_ih_l0, w_ih_l0r, HN, 0, 0,
                          b_ih_l0, b_ih_l0r, b_hh_l0, b_hh_l0r, pG0f, pG0b, HN);

    cudaLaunchKernelEx(&cfg, k_lstm, w_hh_l0, w_hh_l0r, h0, c0, 0);

    k_gemm2<<<gg2, 256>>>(py0, 800, w_ih_l1, w_ih_l1r, 800, 0, 0,
                          b_ih_l1, b_ih_l1r, b_hh_l1, b_hh_l1r, pG1f, pG1b, 800);

    cudaLaunchKernelEx(&cfg, k_lstm, w_hh_l1, w_hh_l1r, h0, c0, 1);

    k_gemm2<<<gg2, 256>>>(phv, 800, mlp_w1, mlp_w1, GN, 0, 800,
                          nullptr, nullptr, nullptr, nullptr, pA, pB, 800);

    k_border<<<1, 352>>>(out);
    k_scores<<<dim3(10, 10), 256>>>(mlp_b1, mlp_w2, mlp_b2, out);
}

// round 10
// speedup vs baseline: 1.1181x; 1.1181x over previous
#include <cuda_runtime.h>
#include <stdint.h>
#include <math.h>

#define SEQN 320
#define HN   400
#define GN   1600
#define NP1  321
#define CLU  16          // CTAs per direction (cluster size, non-portable)
#define DPC  25          // h-dims per CTA
#define TPB  416         // 13 warps; 26 groups of 16 lanes (group 25 is dummy)
#define HPAD 448         // padded h buffer: 16 chunks * 28 floats

// ---------------- scratch (static device globals; no allocation) ----------------
__device__ float g_x[SEQN * HN];
__device__ float g_G0[2][SEQN * GN];
__device__ float g_G1[2][SEQN * GN];
__device__ float g_y0[SEQN * 800];
__device__ float g_hv[SEQN * 800];
__device__ float g_A[SEQN * GN];
__device__ float g_B[SEQN * GN];

// ---------------- embedding gather ----------------
__global__ void k_embed(const int* __restrict__ words, const int* __restrict__ tags,
                        const float* __restrict__ wemb, const float* __restrict__ temb) {
    int idx = blockIdx.x * blockDim.x + threadIdx.x;
    if (idx >= SEQN * HN) return;
    int t = idx / HN, j = idx % HN;
    g_x[idx] = (j < 300) ? wemb[(size_t)words[t] * 300 + j]
                         : temb[(size_t)tags[t] * 100 + (j - 300)];
}

// ---------------- fused dual NT GEMM (64x64 tile — R8-proven) ---------------
__global__ void __launch_bounds__(256)
k_gemm2(const float* __restrict__ X, int ldx,
        const float* __restrict__ W0, const float* __restrict__ W1, int ldw,
        int wofs0, int wofs1,
        const float* __restrict__ b1a, const float* __restrict__ b1b,
        const float* __restrict__ b2a, const float* __restrict__ b2b,
        float* __restrict__ C0, float* __restrict__ C1, int K) {
    const float* W   = blockIdx.z ? W1 : W0;
    const int   wofs = blockIdx.z ? wofs1 : wofs0;
    const float* b1  = blockIdx.z ? b1b : b1a;
    const float* b2  = blockIdx.z ? b2b : b2a;
    float*       C   = blockIdx.z ? C1 : C0;

    __shared__ __align__(16) float Xs[16][64];
    __shared__ __align__(16) float Ws[16][64];
    int tid = threadIdx.x;
    int tx = tid & 15, ty = tid >> 4;
    int row0 = blockIdx.x * 64, col0 = blockIdx.y * 64;
    int lk = tid & 15, lm0 = tid >> 4;

    float acc[4][4] = {};

    for (int k0 = 0; k0 < K; k0 += 16) {
#pragma unroll
        for (int p = 0; p < 4; p++) {
            int m = lm0 + p * 16;
            Xs[lk][m] = X[(size_t)(row0 + m) * ldx + k0 + lk];
            Ws[lk][m] = W[(size_t)(col0 + m) * ldw + wofs + k0 + lk];
        }
        __syncthreads();
#pragma unroll
        for (int kk = 0; kk < 16; kk++) {
            float4 a = *reinterpret_cast<const float4*>(&Xs[kk][ty * 4]);
            float4 b = *reinterpret_cast<const float4*>(&Ws[kk][tx * 4]);
            float av[4] = {a.x, a.y, a.z, a.w};
            float bv[4] = {b.x, b.y, b.z, b.w};
#pragma unroll
            for (int i = 0; i < 4; i++)
#pragma unroll
                for (int j = 0; j < 4; j++)
                    acc[i][j] = fmaf(av[i], bv[j], acc[i][j]);
        }
        __syncthreads();
    }
#pragma unroll
    for (int i = 0; i < 4; i++) {
#pragma unroll
        for (int j = 0; j < 4; j++) {
            int n = col0 + tx * 4 + j;
            float bias = 0.f;
            if (b1) bias += b1[n];
            if (b2) bias += b2[n];
            C[(size_t)(row0 + ty * 4 + i) * GN + n] = acc[i][j] + bias;
        }
    }
}

// ---------------- cluster BiLSTM ----------------
__device__ __forceinline__ float tanh_apx(float x) {
    float y;
    asm("tanh.approx.f32 %0, %1;" : "=f"(y) : "f"(x));
    return y;
}
__device__ __forceinline__ float sig_apx(float x) {
    // sigmoid(x) = 0.5*tanh(x/2) + 0.5
    return fmaf(0.5f, tanh_apx(0.5f * x), 0.5f);
}
__device__ __forceinline__ uint32_t s2u(const void* p) {
    uint32_t a;
    asm("{ .reg .u64 t; cvta.to.shared.u64 t, %1; cvt.u32.u64 %0, t; }" : "=r"(a) : "l"(p));
    return a;
}
__device__ __forceinline__ unsigned long long pack2(float lo, float hi) {
    unsigned long long p;
    asm("mov.b64 %0, {%1, %2};" : "=l"(p) : "f"(lo), "f"(hi));
    return p;
}
__device__ __forceinline__ void fma2(unsigned long long& acc, unsigned long long a,
                                     unsigned long long b) {
    asm("fma.rn.f32x2 %0, %1, %2, %0;" : "+l"(acc) : "l"(a), "l"(b));
}
__device__ __forceinline__ float hsum2(unsigned long long p) {
    float lo, hi;
    asm("mov.b64 {%0, %1}, %2;" : "=f"(lo), "=f"(hi) : "l"(p));
    return lo + hi;
}

// grid (32), cluster (16): blocks 0-15 = forward, 16-31 = backward.
// CTA owns 25 h-dims; thread t: grp = t>>4 (dim), lc = t&15 (25-elem h chunk).
// Dataflow sync: per-source step-counter flags in each CTA's SMEM, published
// with st.release.cluster after a __syncthreads; consumers ld.acquire-poll
// their 16 local slots. No barrier.cluster in the steady state.
__global__ void __launch_bounds__(TPB, 1)
k_lstm(const float* __restrict__ whh_f, const float* __restrict__ whh_b,
       const float* __restrict__ h0, const float* __restrict__ c0, int layer) {
    const int dir = blockIdx.x >> 4;
    const int cta = blockIdx.x & 15;
    const float* G   = (layer == 0) ? g_G0[dir] : g_G1[dir];
    float*       Y   = (layer == 0) ? g_y0 : g_hv;
    const float* whh = dir ? whh_b : whh_f;
    const float* h0row = h0 + (size_t)(2 * layer + dir) * HN;
    const float* c0row = c0 + (size_t)(2 * layer + dir) * HN;

    const int tid = threadIdx.x;
    const int grp = tid >> 4;        // 0..25 (25 = dummy)
    const int lc  = tid & 15;        // h-chunk id
    const bool active = grp < DPC;
    const int dim = cta * DPC + grp;

    __shared__ __align__(16) float sh_h[2][HPAD];
    __shared__ __align__(16) unsigned sh_flag[CLU];   // step count published by src cta

    // ---- register-resident recurrent weights, packed f32x2 (12 pairs + tail) ----
    unsigned long long wI[12], wF[12], wG[12], wO[12];
    float wIt = 0.f, wFt = 0.f, wGt = 0.f, wOt = 0.f;
    if (active) {
        const float* pI = whh + (size_t)(dim)        * HN + lc * 25;
        const float* pF = whh + (size_t)(400 + dim)  * HN + lc * 25;
        const float* pG = whh + (size_t)(800 + dim)  * HN + lc * 25;
        const float* pO = whh + (size_t)(1200 + dim) * HN + lc * 25;
#pragma unroll
        for (int d = 0; d < 12; d++) {
            wI[d] = pack2(__ldg(pI + 2*d), __ldg(pI + 2*d + 1));
            wF[d] = pack2(__ldg(pF + 2*d), __ldg(pF + 2*d + 1));
            wG[d] = pack2(__ldg(pG + 2*d), __ldg(pG + 2*d + 1));
            wO[d] = pack2(__ldg(pO + 2*d), __ldg(pO + 2*d + 1));
        }
        wIt = __ldg(pI + 24); wFt = __ldg(pF + 24);
        wGt = __ldg(pG + 24); wOt = __ldg(pO + 24);
    } else {
#pragma unroll
        for (int d = 0; d < 12; d++) { wI[d] = 0ull; wF[d] = 0ull; wG[d] = 0ull; wO[d] = 0ull; }
    }

    float cst = active ? __ldg(c0row + dim) : 0.f;   // identical across the 16 lanes

    // init buffer 0 with h0 (padded layout) and zero the flags
    for (int i = tid; i < HN; i += TPB)
        sh_h[0][(i / 25) * 28 + (i % 25)] = h0row[i];
    if (tid < CLU) sh_flag[tid] = 0u;
    __syncthreads();

    // one-time cluster barrier: everyone's buffer0 + flags ready before dataflow
    asm volatile("barrier.cluster.arrive.aligned;" ::: "memory");
    asm volatile("barrier.cluster.wait.aligned;" ::: "memory");

    // precomputed remote addresses
    const uint32_t lbase = s2u(&sh_h[0][0]);
    uint32_t raddr0;     // data: rank lc's sh_h slot for my (cta,grp) dim
    {
        uint32_t la = lbase + (uint32_t)((cta * 28 + grp) * 4);
        asm("mapa.shared::cluster.u32 %0, %1, %2;" : "=r"(raddr0) : "r"(la), "r"(lc));
    }
    const uint32_t raddr1 = raddr0 + HPAD * 4;
    uint32_t flag_raddr = 0;   // flag: rank tid's sh_flag[cta]
    if (tid < CLU) {
        uint32_t la = s2u(&sh_flag[cta]);
        asm("mapa.shared::cluster.u32 %0, %1, %2;" : "=r"(flag_raddr) : "r"(la), "r"(tid));
    }
    const uint32_t flag_local = s2u(&sh_flag[0]) + (tid < CLU ? tid * 4u : 0u);

    // prefetch G gates for step 0
    float gi = 0.f, gf = 0.f, gg = 0.f, go = 0.f;
    if (active) {
        const float* gr = G + (size_t)(dir ? SEQN - 1 : 0) * GN + dim;
        gi = __ldg(gr); gf = __ldg(gr + 400); gg = __ldg(gr + 800); go = __ldg(gr + 1200);
    }

    for (int s = 0; s < SEQN; ++s) {
        const int buf = s & 1;
        const int t = dir ? (SEQN - 1 - s) : s;

        // ---- packed dot over this lane's 25-elem chunk ----
        unsigned long long aI = 0ull, aF = 0ull, aG = 0ull, aO = 0ull;
        const ulonglong2* hp = reinterpret_cast<const ulonglong2*>(&sh_h[buf][lc * 28]);
#pragma unroll
        for (int j = 0; j < 6; j++) {
            ulonglong2 v = hp[j];
            fma2(aI, wI[2*j],   v.x); fma2(aF, wF[2*j],   v.x);
            fma2(aG, wG[2*j],   v.x); fma2(aO, wO[2*j],   v.x);
            fma2(aI, wI[2*j+1], v.y); fma2(aF, wF[2*j+1], v.y);
            fma2(aG, wG[2*j+1], v.y); fma2(aO, wO[2*j+1], v.y);
        }
        float ai = hsum2(aI), af = hsum2(aF), ag = hsum2(aG), ao = hsum2(aO);
        {
            float v = sh_h[buf][lc * 28 + 24];
            ai = fmaf(wIt, v, ai); af = fmaf(wFt, v, af);
            ag = fmaf(wGt, v, ag); ao = fmaf(wOt, v, ao);
        }
        // reduce across the 16 lanes of the group
#pragma unroll
        for (int m = 8; m >= 1; m >>= 1) {
            ai += __shfl_xor_sync(0xffffffffu, ai, m);
            af += __shfl_xor_sync(0xffffffffu, af, m);
            ag += __shfl_xor_sync(0xffffffffu, ag, m);
            ao += __shfl_xor_sync(0xffffffffu, ao, m);
        }

        if (active) {
            float I  = sig_apx(gi + ai);
            float F  = sig_apx(gf + af);
            float O  = sig_apx(go + ao);
            float Gv = tanh_apx(gg + ag);
            cst = fmaf(F, cst, I * Gv);
            float hN = O * tanh_apx(cst);
            if (lc == 0) Y[(size_t)t * 800 + dir * HN + dim] = hN;
            // lane lc stores hN into rank lc's next buffer
            uint32_t ra = buf ? raddr0 : raddr1;
            asm volatile("st.shared::cluster.f32 [%0], %1;" :: "r"(ra), "f"(hN) : "memory");
        }

        // prefetch next step's G gates (independent of h)
        if (active && s + 1 < SEQN) {
            const int tn = dir ? (SEQN - 2 - s) : (s + 1);
            const float* gr = G + (size_t)tn * GN + dim;
            gi = __ldg(gr); gf = __ldg(gr + 400); gg = __ldg(gr + 800); go = __ldg(gr + 1200);
        }

        // ---- dataflow step handshake ----
        __syncthreads();   // all data stores issued; all reads of buf done
        if (tid < CLU) {
            // publish step s+1 to rank tid (release orders the data stores above)
            asm volatile("st.release.cluster.shared::cluster.u32 [%0], %1;"
                         :: "r"(flag_raddr), "r"((unsigned)(s + 1)) : "memory");
        }
        if (s + 1 < SEQN) {
            if (tid < CLU) {
                unsigned v;
                do {
                    asm volatile("ld.acquire.cluster.shared::cta.u32 %0, [%1];"
                                 : "=r"(v) : "r"(flag_local) : "memory");
                } while (v < (unsigned)(s + 1));
            }
            __syncthreads();   // poll done before anyone reads the new buffer
        }
    }
}

// ---------------- output border (row 0 / col 0, corner) ----------------
__global__ void k_border(float* __restrict__ out) {
    int i = threadIdx.x;
    if (i < NP1) {
        out[i] = (i == 0) ? 1.f : 0.f;
        if (i > 0) out[(size_t)i * NP1] = 0.f;
    }
}

// ---------------- pairwise scorer ----------------
__global__ void __launch_bounds__(256)
k_scores(const float* __restrict__ b1v, const float* __restrict__ w2,
         const float* __restrict__ b2, float* __restrict__ out) {
    __shared__ float As[32][65];
    __shared__ float Bs[32][65];
    __shared__ float w2s[64];
    int tid = threadIdx.x;
    int tx = tid & 15, ty = tid >> 4;
    int i0 = blockIdx.y * 32, j0 = blockIdx.x * 32;

    float acc[2][2] = {};

    for (int k0 = 0; k0 < GN; k0 += 64) {
        int c = tid & 63;
        int rbase = tid >> 6;
        float bb = __ldg(b1v + k0 + c);
#pragma unroll
        for (int p = 0; p < 8; p++) {
            int rr = rbase + p * 4;
            As[rr][c] = g_A[(size_t)(i0 + rr) * GN + k0 + c] + bb;
            Bs[rr][c] = g_B[(size_t)(j0 + rr) * GN + k0 + c];
        }
        if (tid < 64) w2s[tid] = w2[k0 + tid];
        __syncthreads();
#pragma unroll 8
        for (int kk = 0; kk < 64; kk++) {
            float w  = w2s[kk];
            float a0 = As[2 * ty][kk],  a1  = As[2 * ty + 1][kk];
            float b0 = Bs[2 * tx][kk],  b1_ = Bs[2 * tx + 1][kk];
            acc[0][0] = fmaf(fmaxf(a0 + b0, 0.f), w, acc[0][0]);
            acc[0][1] = fmaf(fmaxf(a0 + b1_, 0.f), w, acc[0][1]);
            acc[1][0] = fmaf(fmaxf(a1 + b0, 0.f), w, acc[1][0]);
            acc[1][1] = fmaf(fmaxf(a1 + b1_, 0.f), w, acc[1][1]);
        }
        __syncthreads();
    }
    float bb2 = __ldg(b2);
#pragma unroll
    for (int ii = 0; ii < 2; ii++)
#pragma unroll
        for (int jj = 0; jj < 2; jj++) {
            int i = i0 + 2 * ty + ii, j = j0 + 2 * tx + jj;
            float v = acc[ii][jj] + bb2;
            if (i == j) v = 0.f;
            out[(size_t)(i + 1) * NP1 + (j + 1)] = v;
        }
}

// ---------------- launch ----------------
extern "C" void kernel_launch(void* const* d_in, const int* in_sizes, int n_in,
                              void* d_out, int out_size) {
    const int*   words    = (const int*)  d_in[0];
    const int*   tags     = (const int*)  d_in[1];
    // d_in[2] = arcs (unused by reference)
    const float* wemb     = (const float*)d_in[3];
    const float* temb     = (const float*)d_in[4];
    const float* h0       = (const float*)d_in[5];
    const float* c0       = (const float*)d_in[6];
    const float* w_ih_l0  = (const float*)d_in[7];
    const float* w_hh_l0  = (const float*)d_in[8];
    const float* b_ih_l0  = (const float*)d_in[9];
    const float* b_hh_l0  = (const float*)d_in[10];
    const float* w_ih_l0r = (const float*)d_in[11];
    const float* w_hh_l0r = (const float*)d_in[12];
    const float* b_ih_l0r = (const float*)d_in[13];
    const float* b_hh_l0r = (const float*)d_in[14];
    const float* w_ih_l1  = (const float*)d_in[15];
    const float* w_hh_l1  = (const float*)d_in[16];
    const float* b_ih_l1  = (const float*)d_in[17];
    const float* b_hh_l1  = (const float*)d_in[18];
    const float* w_ih_l1r = (const float*)d_in[19];
    const float* w_hh_l1r = (const float*)d_in[20];
    const float* b_ih_l1r = (const float*)d_in[21];
    const float* b_hh_l1r = (const float*)d_in[22];
    const float* mlp_w1   = (const float*)d_in[23];
    const float* mlp_b1   = (const float*)d_in[24];
    const float* mlp_w2   = (const float*)d_in[25];
    const float* mlp_b2   = (const float*)d_in[26];
    float* out = (float*)d_out;

    float *px, *pG0, *pG1, *py0, *phv, *pA, *pB;
    cudaGetSymbolAddress((void**)&px,  g_x);
    cudaGetSymbolAddress((void**)&pG0, g_G0);
    cudaGetSymbolAddress((void**)&pG1, g_G1);
    cudaGetSymbolAddress((void**)&py0, g_y0);
    cudaGetSymbolAddress((void**)&phv, g_hv);
    cudaGetSymbolAddress((void**)&pA,  g_A);
    cudaGetSymbolAddress((void**)&pB,  g_B);
    float* pG0f = pG0;
    float* pG0b = pG0 + (size_t)SEQN * GN;
    float* pG1f = pG1;
    float* pG1b = pG1 + (size_t)SEQN * GN;

    static int attr_done = 0;
    if (!attr_done) {
        cudaFuncSetAttribute(k_lstm, cudaFuncAttributeNonPortableClusterSizeAllowed, 1);
        attr_done = 1;
    }
    cudaLaunchConfig_t cfg = {};
    cfg.gridDim  = dim3(2 * CLU, 1, 1);
    cfg.blockDim = dim3(TPB, 1, 1);
    cfg.dynamicSmemBytes = 0;
    cfg.stream = 0;
    cudaLaunchAttribute lat[1];
    lat[0].id = cudaLaunchAttributeClusterDimension;
    lat[0].val.clusterDim.x = CLU;
    lat[0].val.clusterDim.y = 1;
    lat[0].val.clusterDim.z = 1;
    cfg.attrs = lat;
    cfg.numAttrs = 1;

    dim3 gg2(5, 25, 2);   // 320/64 x 1600/64 x 2 fused problems (64x64 tiles)

    k_embed<<<(SEQN * HN + 255) / 256, 256>>>(words, tags, wemb, temb);

    k_gemm2<<<gg2, 256>>>(px, HN, w_ih_l0, w_ih_l0r, HN, 0, 0,
                          b_ih_l0, b_ih_l0r, b_hh_l0, b_hh_l0r, pG0f, pG0b, HN);

    cudaLaunchKernelEx(&cfg, k_lstm, w_hh_l0, w_hh_l0r, h0, c0, 0);

    k_gemm2<<<gg2, 256>>>(py0, 800, w_ih_l1, w_ih_l1r, 800, 0, 0,
                          b_ih_l1, b_ih_l1r, b_hh_l1, b_hh_l1r, pG1f, pG1b, 800);

    cudaLaunchKernelEx(&cfg, k_lstm, w_hh_l1, w_hh_l1r, h0, c0, 1);

    k_gemm2<<<gg2, 256>>>(phv, 800, mlp_w1, mlp_w1, GN, 0, 800,
                          nullptr, nullptr, nullptr, nullptr, pA, pB, 800);

    k_border<<<1, 352>>>(out);
    k_scores<<<dim3(10, 10), 256>>>(mlp_b1, mlp_w2, mlp_b2, out);
}

// round 11
// speedup vs baseline: 1.1754x; 1.0513x over previous
#include <cuda_runtime.h>
#include <stdint.h>
#include <math.h>

#define SEQN 320
#define HN   400
#define GN   1600
#define NP1  321
#define CLU  16          // CTAs per direction (cluster size, non-portable)
#define DPC  25          // h-dims per CTA
#define TPB  416         // 13 warps; 26 groups of 16 lanes (group 25 is dummy)
#define HPAD 448         // padded h buffer: 16 chunks * 28 floats

// ---------------- scratch (static device globals; no allocation) ----------------
__device__ float g_x[SEQN * HN];
__device__ float g_G0[2][SEQN * GN];
__device__ float g_G1[2][SEQN * GN];
__device__ float g_y0[SEQN * 800];
__device__ float g_hv[SEQN * 800];
__device__ float g_A[SEQN * GN];
__device__ float g_B[SEQN * GN];

// ---------------- embedding gather ----------------
__global__ void k_embed(const int* __restrict__ words, const int* __restrict__ tags,
                        const float* __restrict__ wemb, const float* __restrict__ temb) {
    int idx = blockIdx.x * blockDim.x + threadIdx.x;
    if (idx >= SEQN * HN) return;
    int t = idx / HN, j = idx % HN;
    g_x[idx] = (j < 300) ? wemb[(size_t)words[t] * 300 + j]
                         : temb[(size_t)tags[t] * 100 + (j - 300)];
}

// ---------------- fused dual NT GEMM (64x64 tile, double-buffered smem) -----
__global__ void __launch_bounds__(256)
k_gemm2(const float* __restrict__ X, int ldx,
        const float* __restrict__ W0, const float* __restrict__ W1, int ldw,
        int wofs0, int wofs1,
        const float* __restrict__ b1a, const float* __restrict__ b1b,
        const float* __restrict__ b2a, const float* __restrict__ b2b,
        float* __restrict__ C0, float* __restrict__ C1, int K) {
    const float* W   = blockIdx.z ? W1 : W0;
    const int   wofs = blockIdx.z ? wofs1 : wofs0;
    const float* b1  = blockIdx.z ? b1b : b1a;
    const float* b2  = blockIdx.z ? b2b : b2a;
    float*       C   = blockIdx.z ? C1 : C0;

    __shared__ __align__(16) float Xs[2][16][64];
    __shared__ __align__(16) float Ws[2][16][64];
    int tid = threadIdx.x;
    int tx = tid & 15, ty = tid >> 4;
    int row0 = blockIdx.x * 64, col0 = blockIdx.y * 64;
    int lk = tid & 15, lm0 = tid >> 4;

    float acc[4][4] = {};
    const int nch = K / 16;

    // preload chunk 0
#pragma unroll
    for (int p = 0; p < 4; p++) {
        int m = lm0 + p * 16;
        Xs[0][lk][m] = X[(size_t)(row0 + m) * ldx + lk];
        Ws[0][lk][m] = W[(size_t)(col0 + m) * ldw + wofs + lk];
    }
    __syncthreads();

    int cur = 0;
    for (int i = 0; i < nch; i++) {
        // prefetch chunk i+1 into the other buffer (safe: last consumed at i-1,
        // protected by the __syncthreads at the end of iteration i-1)
        if (i + 1 < nch) {
            int k0 = (i + 1) * 16;
#pragma unroll
            for (int p = 0; p < 4; p++) {
                int m = lm0 + p * 16;
                Xs[cur ^ 1][lk][m] = X[(size_t)(row0 + m) * ldx + k0 + lk];
                Ws[cur ^ 1][lk][m] = W[(size_t)(col0 + m) * ldw + wofs + k0 + lk];
            }
        }
#pragma unroll
        for (int kk = 0; kk < 16; kk++) {
            float4 a = *reinterpret_cast<const float4*>(&Xs[cur][kk][ty * 4]);
            float4 b = *reinterpret_cast<const float4*>(&Ws[cur][kk][tx * 4]);
            float av[4] = {a.x, a.y, a.z, a.w};
            float bv[4] = {b.x, b.y, b.z, b.w};
#pragma unroll
            for (int ii = 0; ii < 4; ii++)
#pragma unroll
                for (int j = 0; j < 4; j++)
                    acc[ii][j] = fmaf(av[ii], bv[j], acc[ii][j]);
        }
        __syncthreads();
        cur ^= 1;
    }
#pragma unroll
    for (int i = 0; i < 4; i++) {
#pragma unroll
        for (int j = 0; j < 4; j++) {
            int n = col0 + tx * 4 + j;
            float bias = 0.f;
            if (b1) bias += b1[n];
            if (b2) bias += b2[n];
            C[(size_t)(row0 + ty * 4 + i) * GN + n] = acc[i][j] + bias;
        }
    }
}

// ---------------- cluster BiLSTM ----------------
__device__ __forceinline__ float tanh_apx(float x) {
    float y;
    asm("tanh.approx.f32 %0, %1;" : "=f"(y) : "f"(x));
    return y;
}
__device__ __forceinline__ float sig_apx(float x) {
    return fmaf(0.5f, tanh_apx(0.5f * x), 0.5f);
}
__device__ __forceinline__ uint32_t s2u(const void* p) {
    uint32_t a;
    asm("{ .reg .u64 t; cvta.to.shared.u64 t, %1; cvt.u32.u64 %0, t; }" : "=r"(a) : "l"(p));
    return a;
}
__device__ __forceinline__ unsigned long long pack2(float lo, float hi) {
    unsigned long long p;
    asm("mov.b64 %0, {%1, %2};" : "=l"(p) : "f"(lo), "f"(hi));
    return p;
}
__device__ __forceinline__ void fma2(unsigned long long& acc, unsigned long long a,
                                     unsigned long long b) {
    asm("fma.rn.f32x2 %0, %1, %2, %0;" : "+l"(acc) : "l"(a), "l"(b));
}
__device__ __forceinline__ float hsum2(unsigned long long p) {
    float lo, hi;
    asm("mov.b64 {%0, %1}, %2;" : "=f"(lo), "=f"(hi) : "l"(p));
    return lo + hi;
}

// grid (32), cluster (16): blocks 0-15 = forward, 16-31 = backward.
// CTA owns 25 h-dims; thread t: grp = t>>4 (dim), lc = t&15 (25-elem h chunk).
// G-gate loads deduplicated: lanes lc<4 of each group load one gate each
// (100 LDG/CTA/step instead of 1600), broadcast via shfl.idx.
__global__ void __launch_bounds__(TPB, 1)
k_lstm(const float* __restrict__ whh_f, const float* __restrict__ whh_b,
       const float* __restrict__ h0, const float* __restrict__ c0, int layer) {
    const int dir = blockIdx.x >> 4;
    const int cta = blockIdx.x & 15;
    const float* G   = (layer == 0) ? g_G0[dir] : g_G1[dir];
    float*       Y   = (layer == 0) ? g_y0 : g_hv;
    const float* whh = dir ? whh_b : whh_f;
    const float* h0row = h0 + (size_t)(2 * layer + dir) * HN;
    const float* c0row = c0 + (size_t)(2 * layer + dir) * HN;

    const int tid = threadIdx.x;
    const int grp = tid >> 4;        // 0..25 (25 = dummy)
    const int lc  = tid & 15;        // h-chunk id
    const bool active = grp < DPC;
    const int dim = cta * DPC + grp;
    const int wbase = tid & 16;      // group base lane within warp (0 or 16)

    __shared__ __align__(16) float sh_h[2][HPAD];
    __shared__ __align__(16) unsigned sh_flag[CLU];

    // ---- register-resident recurrent weights, packed f32x2 (12 pairs + tail) ----
    unsigned long long wI[12], wF[12], wG[12], wO[12];
    float wIt = 0.f, wFt = 0.f, wGt = 0.f, wOt = 0.f;
    if (active) {
        const float* pI = whh + (size_t)(dim)        * HN + lc * 25;
        const float* pF = whh + (size_t)(400 + dim)  * HN + lc * 25;
        const float* pG = whh + (size_t)(800 + dim)  * HN + lc * 25;
        const float* pO = whh + (size_t)(1200 + dim) * HN + lc * 25;
#pragma unroll
        for (int d = 0; d < 12; d++) {
            wI[d] = pack2(__ldg(pI + 2*d), __ldg(pI + 2*d + 1));
            wF[d] = pack2(__ldg(pF + 2*d), __ldg(pF + 2*d + 1));
            wG[d] = pack2(__ldg(pG + 2*d), __ldg(pG + 2*d + 1));
            wO[d] = pack2(__ldg(pO + 2*d), __ldg(pO + 2*d + 1));
        }
        wIt = __ldg(pI + 24); wFt = __ldg(pF + 24);
        wGt = __ldg(pG + 24); wOt = __ldg(pO + 24);
    } else {
#pragma unroll
        for (int d = 0; d < 12; d++) { wI[d] = 0ull; wF[d] = 0ull; wG[d] = 0ull; wO[d] = 0ull; }
    }

    float cst = active ? __ldg(c0row + dim) : 0.f;

    // init buffer 0 with h0 (padded layout) and zero the flags
    for (int i = tid; i < HN; i += TPB)
        sh_h[0][(i / 25) * 28 + (i % 25)] = h0row[i];
    if (tid < CLU) sh_flag[tid] = 0u;
    __syncthreads();

    asm volatile("barrier.cluster.arrive.aligned;" ::: "memory");
    asm volatile("barrier.cluster.wait.aligned;" ::: "memory");

    // precomputed remote addresses
    const uint32_t lbase = s2u(&sh_h[0][0]);
    uint32_t raddr0;
    {
        uint32_t la = lbase + (uint32_t)((cta * 28 + grp) * 4);
        asm("mapa.shared::cluster.u32 %0, %1, %2;" : "=r"(raddr0) : "r"(la), "r"(lc));
    }
    const uint32_t raddr1 = raddr0 + HPAD * 4;
    uint32_t flag_raddr = 0;
    if (tid < CLU) {
        uint32_t la = s2u(&sh_flag[cta]);
        asm("mapa.shared::cluster.u32 %0, %1, %2;" : "=r"(flag_raddr) : "r"(la), "r"(tid));
    }
    const uint32_t flag_local = s2u(&sh_flag[0]) + (tid < CLU ? tid * 4u : 0u);

    // prefetch G gate for step 0 — lanes lc<4 load gate lc only
    float gval = 0.f;
    if (active && lc < 4) {
        gval = __ldg(G + (size_t)(dir ? SEQN - 1 : 0) * GN + lc * 400 + dim);
    }

    for (int s = 0; s < SEQN; ++s) {
        const int buf = s & 1;
        const int t = dir ? (SEQN - 1 - s) : s;

        // ---- packed dot over this lane's 25-elem chunk ----
        unsigned long long aI = 0ull, aF = 0ull, aG = 0ull, aO = 0ull;
        const ulonglong2* hp = reinterpret_cast<const ulonglong2*>(&sh_h[buf][lc * 28]);
#pragma unroll
        for (int j = 0; j < 6; j++) {
            ulonglong2 v = hp[j];
            fma2(aI, wI[2*j],   v.x); fma2(aF, wF[2*j],   v.x);
            fma2(aG, wG[2*j],   v.x); fma2(aO, wO[2*j],   v.x);
            fma2(aI, wI[2*j+1], v.y); fma2(aF, wF[2*j+1], v.y);
            fma2(aG, wG[2*j+1], v.y); fma2(aO, wO[2*j+1], v.y);
        }
        float ai = hsum2(aI), af = hsum2(aF), ag = hsum2(aG), ao = hsum2(aO);
        {
            float v = sh_h[buf][lc * 28 + 24];
            ai = fmaf(wIt, v, ai); af = fmaf(wFt, v, af);
            ag = fmaf(wGt, v, ag); ao = fmaf(wOt, v, ao);
        }
        // reduce across the 16 lanes of the group
#pragma unroll
        for (int m = 8; m >= 1; m >>= 1) {
            ai += __shfl_xor_sync(0xffffffffu, ai, m);
            af += __shfl_xor_sync(0xffffffffu, af, m);
            ag += __shfl_xor_sync(0xffffffffu, ag, m);
            ao += __shfl_xor_sync(0xffffffffu, ao, m);
        }

        // broadcast the 4 prefetched G gate values from lanes wbase..wbase+3
        float gi = __shfl_sync(0xffffffffu, gval, wbase + 0);
        float gf = __shfl_sync(0xffffffffu, gval, wbase + 1);
        float gg = __shfl_sync(0xffffffffu, gval, wbase + 2);
        float go = __shfl_sync(0xffffffffu, gval, wbase + 3);

        if (active) {
            float I  = sig_apx(gi + ai);
            float F  = sig_apx(gf + af);
            float O  = sig_apx(go + ao);
            float Gv = tanh_apx(gg + ag);
            cst = fmaf(F, cst, I * Gv);
            float hN = O * tanh_apx(cst);
            if (lc == 0) Y[(size_t)t * 800 + dir * HN + dim] = hN;
            uint32_t ra = buf ? raddr0 : raddr1;
            asm volatile("st.shared::cluster.f32 [%0], %1;" :: "r"(ra), "f"(hN) : "memory");
        }

        // prefetch next step's G gate (lanes lc<4 only; independent of h)
        if (s + 1 < SEQN) {
            if (active && lc < 4) {
                const int tn = dir ? (SEQN - 2 - s) : (s + 1);
                gval = __ldg(G + (size_t)tn * GN + lc * 400 + dim);
            }
        }

        // ---- dataflow step handshake ----
        __syncthreads();
        if (tid < CLU) {
            asm volatile("st.release.cluster.shared::cluster.u32 [%0], %1;"
                         :: "r"(flag_raddr), "r"((unsigned)(s + 1)) : "memory");
        }
        if (s + 1 < SEQN) {
            if (tid < CLU) {
                unsigned v;
                do {
                    asm volatile("ld.acquire.cluster.shared::cta.u32 %0, [%1];"
                                 : "=r"(v) : "r"(flag_local) : "memory");
                } while (v < (unsigned)(s + 1));
            }
            __syncthreads();
        }
    }
}

// ---------------- output border (row 0 / col 0, corner) ----------------
__global__ void k_border(float* __restrict__ out) {
    int i = threadIdx.x;
    if (i < NP1) {
        out[i] = (i == 0) ? 1.f : 0.f;
        if (i > 0) out[(size_t)i * NP1] = 0.f;
    }
}

// ---------------- pairwise scorer ----------------
__global__ void __launch_bounds__(256)
k_scores(const float* __restrict__ b1v, const float* __restrict__ w2,
         const float* __restrict__ b2, float* __restrict__ out) {
    __shared__ float As[32][65];
    __shared__ float Bs[32][65];
    __shared__ float w2s[64];
    int tid = threadIdx.x;
    int tx = tid & 15, ty = tid >> 4;
    int i0 = blockIdx.y * 32, j0 = blockIdx.x * 32;

    float acc[2][2] = {};

    for (int k0 = 0; k0 < GN; k0 += 64) {
        int c = tid & 63;
        int rbase = tid >> 6;
        float bb = __ldg(b1v + k0 + c);
#pragma unroll
        for (int p = 0; p < 8; p++) {
            int rr = rbase + p * 4;
            As[rr][c] = g_A[(size_t)(i0 + rr) * GN + k0 + c] + bb;
            Bs[rr][c] = g_B[(size_t)(j0 + rr) * GN + k0 + c];
        }
        if (tid < 64) w2s[tid] = w2[k0 + tid];
        __syncthreads();
#pragma unroll 8
        for (int kk = 0; kk < 64; kk++) {
            float w  = w2s[kk];
            float a0 = As[2 * ty][kk],  a1  = As[2 * ty + 1][kk];
            float b0 = Bs[2 * tx][kk],  b1_ = Bs[2 * tx + 1][kk];
            acc[0][0] = fmaf(fmaxf(a0 + b0, 0.f), w, acc[0][0]);
            acc[0][1] = fmaf(fmaxf(a0 + b1_, 0.f), w, acc[0][1]);
            acc[1][0] = fmaf(fmaxf(a1 + b0, 0.f), w, acc[1][0]);
            acc[1][1] = fmaf(fmaxf(a1 + b1_, 0.f), w, acc[1][1]);
        }
        __syncthreads();
    }
    float bb2 = __ldg(b2);
#pragma unroll
    for (int ii = 0; ii < 2; ii++)
#pragma unroll
        for (int jj = 0; jj < 2; jj++) {
            int i = i0 + 2 * ty + ii, j = j0 + 2 * tx + jj;
            float v = acc[ii][jj] + bb2;
            if (i == j) v = 0.f;
            out[(size_t)(i + 1) * NP1 + (j + 1)] = v;
        }
}

// ---------------- launch ----------------
extern "C" void kernel_launch(void* const* d_in, const int* in_sizes, int n_in,
                              void* d_out, int out_size) {
    const int*   words    = (const int*)  d_in[0];
    const int*   tags     = (const int*)  d_in[1];
    // d_in[2] = arcs (unused by reference)
    const float* wemb     = (const float*)d_in[3];
    const float* temb     = (const float*)d_in[4];
    const float* h0       = (const float*)d_in[5];
    const float* c0       = (const float*)d_in[6];
    const float* w_ih_l0  = (const float*)d_in[7];
    const float* w_hh_l0  = (const float*)d_in[8];
    const float* b_ih_l0  = (const float*)d_in[9];
    const float* b_hh_l0  = (const float*)d_in[10];
    const float* w_ih_l0r = (const float*)d_in[11];
    const float* w_hh_l0r = (const float*)d_in[12];
    const float* b_ih_l0r = (const float*)d_in[13];
    const float* b_hh_l0r = (const float*)d_in[14];
    const float* w_ih_l1  = (const float*)d_in[15];
    const float* w_hh_l1  = (const float*)d_in[16];
    const float* b_ih_l1  = (const float*)d_in[17];
    const float* b_hh_l1  = (const float*)d_in[18];
    const float* w_ih_l1r = (const float*)d_in[19];
    const float* w_hh_l1r = (const float*)d_in[20];
    const float* b_ih_l1r = (const float*)d_in[21];
    const float* b_hh_l1r = (const float*)d_in[22];
    const float* mlp_w1   = (const float*)d_in[23];
    const float* mlp_b1   = (const float*)d_in[24];
    const float* mlp_w2   = (const float*)d_in[25];
    const float* mlp_b2   = (const float*)d_in[26];
    float* out = (float*)d_out;

    float *px, *pG0, *pG1, *py0, *phv, *pA, *pB;
    cudaGetSymbolAddress((void**)&px,  g_x);
    cudaGetSymbolAddress((void**)&pG0, g_G0);
    cudaGetSymbolAddress((void**)&pG1, g_G1);
    cudaGetSymbolAddress((void**)&py0, g_y0);
    cudaGetSymbolAddress((void**)&phv, g_hv);
    cudaGetSymbolAddress((void**)&pA,  g_A);
    cudaGetSymbolAddress((void**)&pB,  g_B);
    float* pG0f = pG0;
    float* pG0b = pG0 + (size_t)SEQN * GN;
    float* pG1f = pG1;
    float* pG1b = pG1 + (size_t)SEQN * GN;

    static int attr_done = 0;
    if (!attr_done) {
        cudaFuncSetAttribute(k_lstm, cudaFuncAttributeNonPortableClusterSizeAllowed, 1);
        attr_done = 1;
    }
    cudaLaunchConfig_t cfg = {};
    cfg.gridDim  = dim3(2 * CLU, 1, 1);
    cfg.blockDim = dim3(TPB, 1, 1);
    cfg.dynamicSmemBytes = 0;
    cfg.stream = 0;
    cudaLaunchAttribute lat[1];
    lat[0].id = cudaLaunchAttributeClusterDimension;
    lat[0].val.clusterDim.x = CLU;
    lat[0].val.clusterDim.y = 1;
    lat[0].val.clusterDim.z = 1;
    cfg.attrs = lat;
    cfg.numAttrs = 1;

    dim3 gg2(5, 25, 2);   // 320/64 x 1600/64 x 2 fused problems (64x64 tiles)

    k_embed<<<(SEQN * HN + 255) / 256, 256>>>(words, tags, wemb, temb);

    k_gemm2<<<gg2, 256>>>(px, HN, w_ih_l0, w_ih_l0r, HN, 0, 0,
                          b_ih_l0, b_ih_l0r, b_hh_l0, b_hh_l0r, pG0f, pG0b, HN);

    cudaLaunchKernelEx(&cfg, k_lstm, w_hh_l0, w_hh_l0r, h0, c0, 0);

    k_gemm2<<<gg2, 256>>>(py0, 800, w_ih_l1, w_ih_l1r, 800, 0, 0,
                          b_ih_l1, b_ih_l1r, b_hh_l1, b_hh_l1r, pG1f, pG1b, 800);

    cudaLaunchKernelEx(&cfg, k_lstm, w_hh_l1, w_hh_l1r, h0, c0, 1);

    k_gemm2<<<gg2, 256>>>(phv, 800, mlp_w1, mlp_w1, GN, 0, 800,
                          nullptr, nullptr, nullptr, nullptr, pA, pB, 800);

    k_border<<<1, 352>>>(out);
    k_scores<<<dim3(10, 10), 256>>>(mlp_b1, mlp_w2, mlp_b2, out);
}